// round 14
// baseline (speedup 1.0000x reference)
#include <cuda_runtime.h>
#include <cuda_bf16.h>

#define Bn 8
#define Hn 56
#define Wn 56
#define Cn 64
#define Nn (Hn*Wn)      // 3136
#define En 64
#define NT 49           // 3136/64 k-tiles

// Q fp32 [b][n][c], pre-scaled by 8*log2(e) so P = 2^S.
// K hi/lo: bf16 [b][n][c]   (ldmatrix rows = keys)
// V hi/lo: bf16 [b][c][n]   (ldmatrix rows = chans)
__device__ float         g_Q [Bn*Nn*Cn];
__device__ __nv_bfloat16 g_Kh[Bn*Nn*Cn];
__device__ __nv_bfloat16 g_Kl[Bn*Nn*Cn];
__device__ __nv_bfloat16 g_Vh[Bn*Cn*Nn];
__device__ __nv_bfloat16 g_Vl[Bn*Cn*Nn];

#define QSCALE 11.54156036376953125f   // 8 * log2(e)

// ---------------------------------------------------------------------------
// Kernel 1: depthwise 3x3 conv; float4 compute, row staged in smem.
// ---------------------------------------------------------------------------
#define RS 65

__global__ __launch_bounds__(256) void qkv_conv_kernel(
    const float* __restrict__ x,
    const float* __restrict__ wq, const float* __restrict__ bq,
    const float* __restrict__ wk, const float* __restrict__ bk,
    const float* __restrict__ wv, const float* __restrict__ bv)
{
    extern __shared__ float csm[];
    float* swq = csm;
    float* swk = swq + 9*Cn;
    float* swv = swk + 9*Cn;
    float* qrow = swv + 9*Cn;
    float* krow = qrow + Wn*RS;
    float* vrow = krow + Wn*RS;

    const int b = blockIdx.x / Hn;
    const int h = blockIdx.x % Hn;
    for (int i = threadIdx.x; i < 9*Cn; i += 256) {
        swq[i] = wq[i]; swk[i] = wk[i]; swv[i] = wv[i];
    }
    __syncthreads();

    for (int idx = threadIdx.x; idx < Wn*(Cn/4); idx += 256) {
        const int w  = idx >> 4;
        const int c4 = (idx & 15) << 2;
        float4 aq = *(const float4*)&bq[c4];
        float4 ak = *(const float4*)&bk[c4];
        float4 av = *(const float4*)&bv[c4];
        #pragma unroll
        for (int dh = 0; dh < 3; dh++) {
            const int hh = h + dh - 1;
            if (hh < 0 || hh >= Hn) continue;
            #pragma unroll
            for (int dw = 0; dw < 3; dw++) {
                const int ww = w + dw - 1;
                if (ww < 0 || ww >= Wn) continue;
                const float4 xv = *(const float4*)&x[((b*Hn + hh)*Wn + ww)*Cn + c4];
                const int wi = (dh*3 + dw)*Cn + c4;
                const float4 q4 = *(const float4*)&swq[wi];
                const float4 k4 = *(const float4*)&swk[wi];
                const float4 v4 = *(const float4*)&swv[wi];
                aq.x = fmaf(q4.x, xv.x, aq.x); aq.y = fmaf(q4.y, xv.y, aq.y);
                aq.z = fmaf(q4.z, xv.z, aq.z); aq.w = fmaf(q4.w, xv.w, aq.w);
                ak.x = fmaf(k4.x, xv.x, ak.x); ak.y = fmaf(k4.y, xv.y, ak.y);
                ak.z = fmaf(k4.z, xv.z, ak.z); ak.w = fmaf(k4.w, xv.w, ak.w);
                av.x = fmaf(v4.x, xv.x, av.x); av.y = fmaf(v4.y, xv.y, av.y);
                av.z = fmaf(v4.z, xv.z, av.z); av.w = fmaf(v4.w, xv.w, av.w);
            }
        }
        float* qd = &qrow[w*RS + c4];
        qd[0] = aq.x*QSCALE; qd[1] = aq.y*QSCALE; qd[2] = aq.z*QSCALE; qd[3] = aq.w*QSCALE;
        float* kd = &krow[w*RS + c4];
        kd[0] = ak.x; kd[1] = ak.y; kd[2] = ak.z; kd[3] = ak.w;
        float* vd = &vrow[w*RS + c4];
        vd[0] = av.x; vd[1] = av.y; vd[2] = av.z; vd[3] = av.w;
    }
    __syncthreads();

    {   // Q writer: [b][n][c]
        float* dst = g_Q + ((size_t)b*Nn + h*Wn)*Cn;
        for (int idx = threadIdx.x; idx < Wn*Cn; idx += 256)
            dst[idx] = qrow[(idx >> 6)*RS + (idx & 63)];
    }
    {   // K writer: bf16 hi/lo [b][n][c]
        __nv_bfloat16* dh_ = g_Kh + ((size_t)b*Nn + h*Wn)*Cn;
        __nv_bfloat16* dl_ = g_Kl + ((size_t)b*Nn + h*Wn)*Cn;
        for (int i = threadIdx.x; i < Wn*Cn; i += 256) {
            const float k = krow[(i >> 6)*RS + (i & 63)];
            __nv_bfloat16 hb = __float2bfloat16(k);
            dh_[i] = hb;
            dl_[i] = __float2bfloat16(k - __bfloat162float(hb));
        }
    }
    {   // V writer: bf16 hi/lo [b][c][n]
        __nv_bfloat16* dh_ = g_Vh + (size_t)b*Cn*Nn + h*Wn;
        __nv_bfloat16* dl_ = g_Vl + (size_t)b*Cn*Nn + h*Wn;
        for (int i = threadIdx.x; i < Cn*Wn; i += 256) {
            const int c = i / Wn;
            const int w = i - c*Wn;
            const float v = vrow[w*RS + c];
            __nv_bfloat16 hb = __float2bfloat16(v);
            dh_[(size_t)c*Nn + w] = hb;
            dl_[(size_t)c*Nn + w] = __float2bfloat16(v - __bfloat162float(hb));
        }
    }
}

// ---------------------------------------------------------------------------
// Kernel 2: flash attention. 2 warps/CTA, m32 per warp (2 m-tiles share every
// B fragment -> half the LDSM traffic per MMA). CTA = 64 q-rows, grid (49, 8).
// 3 CTAs/SM by smem (64 KB); 64-thread CTAs mean regs never limit occupancy.
// ---------------------------------------------------------------------------
#define MMA(d, a, b0, b1) \
  asm volatile("mma.sync.aligned.m16n8k16.row.col.f32.bf16.bf16.f32 " \
    "{%0,%1,%2,%3}, {%4,%5,%6,%7}, {%8,%9}, {%0,%1,%2,%3};" \
    : "+f"(d[0]), "+f"(d[1]), "+f"(d[2]), "+f"(d[3]) \
    : "r"(a[0]), "r"(a[1]), "r"(a[2]), "r"(a[3]), "r"(b0), "r"(b1))

__device__ __forceinline__ float ex2(float x) {
    float r;
    asm("ex2.approx.f32 %0, %1;" : "=f"(r) : "f"(x));
    return r;
}

__device__ __forceinline__ void bsplit2(float vx, float vy, unsigned& h, unsigned& l) {
    __nv_bfloat162 H = __floats2bfloat162_rn(vx, vy);
    float2 hf = __bfloat1622float2(H);
    __nv_bfloat162 L = __floats2bfloat162_rn(vx - hf.x, vy - hf.y);
    h = *(unsigned*)&H;
    l = *(unsigned*)&L;
}

__device__ __forceinline__ void cpa16(unsigned* dst, const uint4* src) {
    unsigned s = (unsigned)__cvta_generic_to_shared(dst);
    asm volatile("cp.async.cg.shared.global [%0], [%1], 16;" :: "r"(s), "l"(src));
}

__device__ __forceinline__ void ldsm4(unsigned& r0, unsigned& r1, unsigned& r2,
                                      unsigned& r3, const unsigned* p) {
    unsigned a = (unsigned)__cvta_generic_to_shared(p);
    asm volatile("ldmatrix.sync.aligned.m8n8.x4.shared.b16 {%0,%1,%2,%3}, [%4];"
        : "=r"(r0), "=r"(r1), "=r"(r2), "=r"(r3) : "r"(a));
}

// 12 MMAs (2 m-tiles x 3 products x 2 j) off ONE pair of B-fragment loads
#define PAIR3_2M(Aa0, Aa1, Ab0, Ab1, AHa, ALa, AHb, ALb, PH, PL) do { \
    unsigned h0, h1, h2, h3, u0, u1, u2, u3; \
    ldsm4(h0, h1, h2, h3, PH); \
    ldsm4(u0, u1, u2, u3, PL); \
    MMA(Aa0, AHa, h0, h1);  MMA(Aa1, AHa, h2, h3); \
    MMA(Ab0, AHb, h0, h1);  MMA(Ab1, AHb, h2, h3); \
    MMA(Aa0, ALa, h0, h1);  MMA(Aa1, ALa, h2, h3); \
    MMA(Ab0, ALb, h0, h1);  MMA(Ab1, ALb, h2, h3); \
    MMA(Aa0, AHa, u0, u1);  MMA(Aa1, AHa, u2, u3); \
    MMA(Ab0, AHb, u0, u1);  MMA(Ab1, AHb, u2, u3); \
} while (0)

__global__ __launch_bounds__(64, 3) void attn_kernel(
    const float* __restrict__ Wp, const float* __restrict__ bp,
    float* __restrict__ out)
{
    extern __shared__ unsigned smem[];   // 2 x 8192 words: [Kh|Kl|Vh|Vl] x 2048

    const int b    = blockIdx.y;
    const int q0   = blockIdx.x * 64;
    const int tid  = threadIdx.x;
    const int w    = tid >> 5;          // 0..1
    const int lane = tid & 31;
    const int gr   = lane >> 2;
    const int q    = lane & 3;

    const int sw    = lane & 7;
    const int rbase = (8*(lane >> 4) + sw) * 32;
    const int kb    = (lane >> 3) & 1;

    // ---- Q fragments (hi/lo) for 2 m-tiles: rows q0+32w+{gr,gr+8 | gr+16,gr+24}
    const float* Qb = g_Q + ((size_t)(b*Nn + q0 + 32*w))*Cn;
    unsigned aQh[2][4][4], aQl[2][4][4];
    #pragma unroll
    for (int m = 0; m < 2; m++) {
        const float* r0 = Qb + (16*m + gr)*64;
        const float* r1 = r0 + 8*64;
        #pragma unroll
        for (int ks = 0; ks < 4; ks++) {
            float2 v;
            v = *(const float2*)(r0 + 16*ks + 2*q);     bsplit2(v.x, v.y, aQh[m][ks][0], aQl[m][ks][0]);
            v = *(const float2*)(r1 + 16*ks + 2*q);     bsplit2(v.x, v.y, aQh[m][ks][1], aQl[m][ks][1]);
            v = *(const float2*)(r0 + 16*ks + 8 + 2*q); bsplit2(v.x, v.y, aQh[m][ks][2], aQl[m][ks][2]);
            v = *(const float2*)(r1 + 16*ks + 8 + 2*q); bsplit2(v.x, v.y, aQh[m][ks][3], aQl[m][ks][3]);
        }
    }

    float oA[2][8][4];
    #pragma unroll
    for (int m = 0; m < 2; m++)
        #pragma unroll
        for (int j = 0; j < 8; j++)
            #pragma unroll
            for (int i = 0; i < 4; i++) oA[m][j][i] = 0.0f;
    float lsum[4] = {0.f, 0.f, 0.f, 0.f};   // rows gr, gr+8, gr+16, gr+24

    const uint4* Kh4 = (const uint4*)(g_Kh + (size_t)b*Nn*Cn);
    const uint4* Kl4 = (const uint4*)(g_Kl + (size_t)b*Nn*Cn);
    const uint4* Vh4 = (const uint4*)(g_Vh + (size_t)b*Cn*Nn);
    const uint4* Vl4 = (const uint4*)(g_Vl + (size_t)b*Cn*Nn);

    auto issue_tile = [&](int kt, int bufsel) {
        unsigned* base = smem + bufsel*8192;
        #pragma unroll
        for (int it = 0; it < 8; it++) {
            const int f   = tid + it*64;
            const int row = f >> 3;            // 0..63
            const int ch  = f & 7;
            const int dw  = row*32 + ((ch ^ (row & 7)) << 2);
            cpa16(&base[dw],        Kh4 + kt*512 + row*8 + ch);
            cpa16(&base[2048 + dw], Kl4 + kt*512 + row*8 + ch);
            cpa16(&base[4096 + dw], Vh4 + row*(Nn/8) + kt*8 + ch);
            cpa16(&base[6144 + dw], Vl4 + row*(Nn/8) + kt*8 + ch);
        }
        asm volatile("cp.async.commit_group;" ::: "memory");
    };

    issue_tile(0, 0);
    int buf = 0;

    for (int kt = 0; kt < NT; kt++) {
        asm volatile("cp.async.wait_group 0;" ::: "memory");
        __syncthreads();
        if (kt + 1 < NT) issue_tile(kt + 1, buf ^ 1);

        const unsigned* sKh = smem + buf*8192;
        const unsigned* sVh = sKh + 4096;

        // ---- fused: per 16-key block: S (2 m-tiles) -> exp -> PV k-step ----
        #pragma unroll 1
        for (int jp = 0; jp < 4; jp++) {
            float sa0[4] = {0.f,0.f,0.f,0.f}, sa1[4] = {0.f,0.f,0.f,0.f};
            float sb0[4] = {0.f,0.f,0.f,0.f}, sb1[4] = {0.f,0.f,0.f,0.f};
            #pragma unroll
            for (int ks = 0; ks < 4; ks++) {
                const int co = (((2*ks + kb) ^ sw) << 2) + rbase;
                const unsigned* p = sKh + jp*512 + co;
                PAIR3_2M(sa0, sa1, sb0, sb1,
                         aQh[0][ks], aQl[0][ks], aQh[1][ks], aQl[1][ks],
                         p, p + 2048);
            }

            #pragma unroll
            for (int i = 0; i < 4; i++) sa0[i] = ex2(sa0[i]);
            #pragma unroll
            for (int i = 0; i < 4; i++) sa1[i] = ex2(sa1[i]);
            #pragma unroll
            for (int i = 0; i < 4; i++) sb0[i] = ex2(sb0[i]);
            #pragma unroll
            for (int i = 0; i < 4; i++) sb1[i] = ex2(sb1[i]);
            lsum[0] += sa0[0] + sa0[1] + sa1[0] + sa1[1];
            lsum[1] += sa0[2] + sa0[3] + sa1[2] + sa1[3];
            lsum[2] += sb0[0] + sb0[1] + sb1[0] + sb1[1];
            lsum[3] += sb0[2] + sb0[3] + sb1[2] + sb1[3];

            unsigned aPha[4], aPla[4], aPhb[4], aPlb[4];
            bsplit2(sa0[0], sa0[1], aPha[0], aPla[0]);
            bsplit2(sa0[2], sa0[3], aPha[1], aPla[1]);
            bsplit2(sa1[0], sa1[1], aPha[2], aPla[2]);
            bsplit2(sa1[2], sa1[3], aPha[3], aPla[3]);
            bsplit2(sb0[0], sb0[1], aPhb[0], aPlb[0]);
            bsplit2(sb0[2], sb0[3], aPhb[1], aPlb[1]);
            bsplit2(sb1[0], sb1[1], aPhb[2], aPlb[2]);
            bsplit2(sb1[2], sb1[3], aPhb[3], aPlb[3]);

            const int cov = (((2*jp + kb) ^ sw) << 2) + rbase;
            #pragma unroll
            for (int jv = 0; jv < 4; jv++) {
                const unsigned* p = sVh + jv*512 + cov;
                PAIR3_2M(oA[0][2*jv], oA[0][2*jv + 1], oA[1][2*jv], oA[1][2*jv + 1],
                         aPha, aPla, aPhb, aPlb, p, p + 2048);
            }
        }

        buf ^= 1;
    }

    // ============= epilogue: normalize, project per m-tile =============
    #pragma unroll
    for (int i = 0; i < 4; i++) {
        lsum[i] += __shfl_xor_sync(0xffffffffu, lsum[i], 1);
        lsum[i] += __shfl_xor_sync(0xffffffffu, lsum[i], 2);
        lsum[i] = 1.0f / lsum[i];
    }

    __syncthreads();
    __nv_bfloat16* sWh = (__nv_bfloat16*)smem;
    __nv_bfloat16* sWl = (__nv_bfloat16*)(smem + 2048);
    for (int i = tid; i < 4096; i += 64) {
        const int c = i >> 6, e = i & 63;
        const float wv = Wp[i];
        __nv_bfloat16 hb = __float2bfloat16(wv);
        const int o = e*64 + ((((c >> 3) ^ (e & 7))) << 3) + (c & 7);
        sWh[o] = hb;
        sWl[o] = __float2bfloat16(wv - __bfloat162float(hb));
    }
    __syncthreads();

    #pragma unroll 1
    for (int m = 0; m < 2; m++) {
        const float inv0 = lsum[2*m];
        const float inv1 = lsum[2*m + 1];
        float pA[8][4];
        #pragma unroll
        for (int j = 0; j < 8; j++)
            #pragma unroll
            for (int i = 0; i < 4; i++) pA[j][i] = 0.0f;
        #pragma unroll
        for (int ks = 0; ks < 4; ks++) {
            unsigned aCh[4], aCl[4];
            bsplit2(oA[m][2*ks    ][0]*inv0, oA[m][2*ks    ][1]*inv0, aCh[0], aCl[0]);
            bsplit2(oA[m][2*ks    ][2]*inv1, oA[m][2*ks    ][3]*inv1, aCh[1], aCl[1]);
            bsplit2(oA[m][2*ks + 1][0]*inv0, oA[m][2*ks + 1][1]*inv0, aCh[2], aCl[2]);
            bsplit2(oA[m][2*ks + 1][2]*inv1, oA[m][2*ks + 1][3]*inv1, aCh[3], aCl[3]);
            const int co = (((2*ks + kb) ^ sw) << 2) + rbase;
            #pragma unroll
            for (int jp = 0; jp < 4; jp++) {
                const unsigned* p = smem + jp*512 + co;
                unsigned h0, h1, h2, h3, u0, u1, u2, u3;
                ldsm4(h0, h1, h2, h3, p);
                ldsm4(u0, u1, u2, u3, p + 2048);
                MMA(pA[2*jp    ], aCh, h0, h1);  MMA(pA[2*jp + 1], aCh, h2, h3);
                MMA(pA[2*jp    ], aCl, h0, h1);  MMA(pA[2*jp + 1], aCl, h2, h3);
                MMA(pA[2*jp    ], aCh, u0, u1);  MMA(pA[2*jp + 1], aCh, u2, u3);
            }
        }

        const int row0 = q0 + 32*w + 16*m + gr;
        float* orow0 = out + ((size_t)b*Nn + row0)*En;
        float* orow1 = orow0 + 8*En;
        #pragma unroll
        for (int j = 0; j < 8; j++) {
            const float2 bv = *(const float2*)&bp[8*j + 2*q];
            *(float2*)&orow0[8*j + 2*q] = make_float2(pA[j][0] + bv.x, pA[j][1] + bv.y);
            *(float2*)&orow1[8*j + 2*q] = make_float2(pA[j][2] + bv.x, pA[j][3] + bv.y);
        }
    }
}

// ---------------------------------------------------------------------------
extern "C" void kernel_launch(void* const* d_in, const int* in_sizes, int n_in,
                              void* d_out, int out_size)
{
    const float* x  = (const float*)d_in[0];
    const float* wq = (const float*)d_in[1];
    const float* bq = (const float*)d_in[2];
    const float* wk = (const float*)d_in[3];
    const float* bk = (const float*)d_in[4];
    const float* wv = (const float*)d_in[5];
    const float* bv = (const float*)d_in[6];
    const float* Wp = (const float*)d_in[7];
    const float* bp = (const float*)d_in[8];
    float* out = (float*)d_out;

    const int conv_smem = (27*Cn + 3*Wn*RS) * 4;   // 50592
    cudaFuncSetAttribute(qkv_conv_kernel,
                         cudaFuncAttributeMaxDynamicSharedMemorySize, conv_smem);
    const int smem_bytes = 2*8192*4;   // 65536
    cudaFuncSetAttribute(attn_kernel,
                         cudaFuncAttributeMaxDynamicSharedMemorySize, smem_bytes);

    qkv_conv_kernel<<<Bn*Hn, 256, conv_smem>>>(x, wq, bq, wk, bk, wv, bv);

    dim3 grid(NT, Bn);
    attn_kernel<<<grid, 64, smem_bytes>>>(Wp, bp, out);
}

// round 15
// speedup vs baseline: 1.6958x; 1.6958x over previous
#include <cuda_runtime.h>
#include <cuda_bf16.h>

#define Bn 8
#define Hn 56
#define Wn 56
#define Cn 64
#define Nn (Hn*Wn)      // 3136
#define En 64
#define NT 49           // 3136/64 k-tiles

// Q fp32, pre-scaled by 8*log2(e) so P = 2^S (ex2.approx).
// K hi/lo: bf16 [b][n][c]   (ldmatrix rows = keys)
// V hi/lo: bf16 [b][c][n]   (ldmatrix rows = chans)
__device__ float         g_Q [Bn*Nn*Cn];
__device__ __nv_bfloat16 g_Kh[Bn*Nn*Cn];
__device__ __nv_bfloat16 g_Kl[Bn*Nn*Cn];
__device__ __nv_bfloat16 g_Vh[Bn*Cn*Nn];
__device__ __nv_bfloat16 g_Vl[Bn*Cn*Nn];

#define QSCALE 11.54156036376953125f   // 8 * log2(e)

// ---------------------------------------------------------------------------
// Kernel 1: depthwise 3x3 conv; float4 compute, row staged in smem.
// ---------------------------------------------------------------------------
#define RS 65

__global__ __launch_bounds__(256) void qkv_conv_kernel(
    const float* __restrict__ x,
    const float* __restrict__ wq, const float* __restrict__ bq,
    const float* __restrict__ wk, const float* __restrict__ bk,
    const float* __restrict__ wv, const float* __restrict__ bv)
{
    extern __shared__ float csm[];
    float* swq = csm;
    float* swk = swq + 9*Cn;
    float* swv = swk + 9*Cn;
    float* qrow = swv + 9*Cn;
    float* krow = qrow + Wn*RS;
    float* vrow = krow + Wn*RS;

    const int b = blockIdx.x / Hn;
    const int h = blockIdx.x % Hn;
    for (int i = threadIdx.x; i < 9*Cn; i += 256) {
        swq[i] = wq[i]; swk[i] = wk[i]; swv[i] = wv[i];
    }
    __syncthreads();

    for (int idx = threadIdx.x; idx < Wn*(Cn/4); idx += 256) {
        const int w  = idx >> 4;
        const int c4 = (idx & 15) << 2;
        float4 aq = *(const float4*)&bq[c4];
        float4 ak = *(const float4*)&bk[c4];
        float4 av = *(const float4*)&bv[c4];
        #pragma unroll
        for (int dh = 0; dh < 3; dh++) {
            const int hh = h + dh - 1;
            if (hh < 0 || hh >= Hn) continue;
            #pragma unroll
            for (int dw = 0; dw < 3; dw++) {
                const int ww = w + dw - 1;
                if (ww < 0 || ww >= Wn) continue;
                const float4 xv = *(const float4*)&x[((b*Hn + hh)*Wn + ww)*Cn + c4];
                const int wi = (dh*3 + dw)*Cn + c4;
                const float4 q4 = *(const float4*)&swq[wi];
                const float4 k4 = *(const float4*)&swk[wi];
                const float4 v4 = *(const float4*)&swv[wi];
                aq.x = fmaf(q4.x, xv.x, aq.x); aq.y = fmaf(q4.y, xv.y, aq.y);
                aq.z = fmaf(q4.z, xv.z, aq.z); aq.w = fmaf(q4.w, xv.w, aq.w);
                ak.x = fmaf(k4.x, xv.x, ak.x); ak.y = fmaf(k4.y, xv.y, ak.y);
                ak.z = fmaf(k4.z, xv.z, ak.z); ak.w = fmaf(k4.w, xv.w, ak.w);
                av.x = fmaf(v4.x, xv.x, av.x); av.y = fmaf(v4.y, xv.y, av.y);
                av.z = fmaf(v4.z, xv.z, av.z); av.w = fmaf(v4.w, xv.w, av.w);
            }
        }
        float* qd = &qrow[w*RS + c4];
        qd[0] = aq.x*QSCALE; qd[1] = aq.y*QSCALE; qd[2] = aq.z*QSCALE; qd[3] = aq.w*QSCALE;
        float* kd = &krow[w*RS + c4];
        kd[0] = ak.x; kd[1] = ak.y; kd[2] = ak.z; kd[3] = ak.w;
        float* vd = &vrow[w*RS + c4];
        vd[0] = av.x; vd[1] = av.y; vd[2] = av.z; vd[3] = av.w;
    }
    __syncthreads();

    {   // Q writer: [b][n][c]
        float* dst = g_Q + ((size_t)b*Nn + h*Wn)*Cn;
        for (int idx = threadIdx.x; idx < Wn*Cn; idx += 256)
            dst[idx] = qrow[(idx >> 6)*RS + (idx & 63)];
    }
    {   // K writer: bf16 hi/lo [b][n][c]
        __nv_bfloat16* dh_ = g_Kh + ((size_t)b*Nn + h*Wn)*Cn;
        __nv_bfloat16* dl_ = g_Kl + ((size_t)b*Nn + h*Wn)*Cn;
        for (int i = threadIdx.x; i < Wn*Cn; i += 256) {
            const float k = krow[(i >> 6)*RS + (i & 63)];
            __nv_bfloat16 hb = __float2bfloat16(k);
            dh_[i] = hb;
            dl_[i] = __float2bfloat16(k - __bfloat162float(hb));
        }
    }
    {   // V writer: bf16 hi/lo [b][c][n]
        __nv_bfloat16* dh_ = g_Vh + (size_t)b*Cn*Nn + h*Wn;
        __nv_bfloat16* dl_ = g_Vl + (size_t)b*Cn*Nn + h*Wn;
        for (int i = threadIdx.x; i < Cn*Wn; i += 256) {
            const int c = i / Wn;
            const int w = i - c*Wn;
            const float v = vrow[w*RS + c];
            __nv_bfloat16 hb = __float2bfloat16(v);
            dh_[(size_t)c*Nn + w] = hb;
            dl_[(size_t)c*Nn + w] = __float2bfloat16(v - __bfloat162float(hb));
        }
    }
}

// ---------------------------------------------------------------------------
// Kernel 2: flash attention (no-max base-2 softmax) + projection.
// jp processed in PAIRS: S for 2 key-blocks (4 accumulator chains) -> exp ->
// 2 PV k-steps. Same accumulation order as the fused single-jp version.
// ---------------------------------------------------------------------------
#define MMA(d, a, b0, b1) \
  asm volatile("mma.sync.aligned.m16n8k16.row.col.f32.bf16.bf16.f32 " \
    "{%0,%1,%2,%3}, {%4,%5,%6,%7}, {%8,%9}, {%0,%1,%2,%3};" \
    : "+f"(d[0]), "+f"(d[1]), "+f"(d[2]), "+f"(d[3]) \
    : "r"(a[0]), "r"(a[1]), "r"(a[2]), "r"(a[3]), "r"(b0), "r"(b1))

__device__ __forceinline__ float ex2(float x) {
    float r;
    asm("ex2.approx.f32 %0, %1;" : "=f"(r) : "f"(x));
    return r;
}

__device__ __forceinline__ void bsplit2(float vx, float vy, unsigned& h, unsigned& l) {
    __nv_bfloat162 H = __floats2bfloat162_rn(vx, vy);
    float2 hf = __bfloat1622float2(H);
    __nv_bfloat162 L = __floats2bfloat162_rn(vx - hf.x, vy - hf.y);
    h = *(unsigned*)&H;
    l = *(unsigned*)&L;
}

__device__ __forceinline__ void cpa16(unsigned* dst, const uint4* src) {
    unsigned s = (unsigned)__cvta_generic_to_shared(dst);
    asm volatile("cp.async.cg.shared.global [%0], [%1], 16;" :: "r"(s), "l"(src));
}

__device__ __forceinline__ void ldsm4(unsigned& r0, unsigned& r1, unsigned& r2,
                                      unsigned& r3, const unsigned* p) {
    unsigned a = (unsigned)__cvta_generic_to_shared(p);
    asm volatile("ldmatrix.sync.aligned.m8n8.x4.shared.b16 {%0,%1,%2,%3}, [%4];"
        : "=r"(r0), "=r"(r1), "=r"(r2), "=r"(r3) : "r"(a));
}

#define PAIR3(A0, A1, AH, AL, PH, PL) do { \
    unsigned h0, h1, h2, h3, u0, u1, u2, u3; \
    ldsm4(h0, h1, h2, h3, PH); \
    ldsm4(u0, u1, u2, u3, PL); \
    MMA(A0, AH, h0, h1);  MMA(A1, AH, h2, h3); \
    MMA(A0, AL, h0, h1);  MMA(A1, AL, h2, h3); \
    MMA(A0, AH, u0, u1);  MMA(A1, AH, u2, u3); \
} while (0)

// Two PAIR3s on independent accumulator pairs, interleaved for ILP
#define PAIR3_X2(A0, A1, B0, B1, AH, AL, PH0, PL0, PH1, PL1) do { \
    unsigned a0, a1, a2, a3, b0_, b1_, b2_, b3_; \
    unsigned c0, c1, c2, c3, d0_, d1_, d2_, d3_; \
    ldsm4(a0, a1, a2, a3, PH0); \
    ldsm4(c0, c1, c2, c3, PH1); \
    ldsm4(b0_, b1_, b2_, b3_, PL0); \
    ldsm4(d0_, d1_, d2_, d3_, PL1); \
    MMA(A0, AH, a0, a1);  MMA(B0, AH, c0, c1); \
    MMA(A1, AH, a2, a3);  MMA(B1, AH, c2, c3); \
    MMA(A0, AL, a0, a1);  MMA(B0, AL, c0, c1); \
    MMA(A1, AL, a2, a3);  MMA(B1, AL, c2, c3); \
    MMA(A0, AH, b0_, b1_);  MMA(B0, AH, d0_, d1_); \
    MMA(A1, AH, b2_, b3_);  MMA(B1, AH, d2_, d3_); \
} while (0)

__global__ __launch_bounds__(128, 3) void attn_kernel(
    const float* __restrict__ Wp, const float* __restrict__ bp,
    float* __restrict__ out)
{
    extern __shared__ unsigned smem[];   // 2 x 8192 words: [Kh|Kl|Vh|Vl] x 2048

    const int b    = blockIdx.y;
    const int q0   = blockIdx.x * 64;
    const int tid  = threadIdx.x;
    const int wp   = tid >> 5;
    const int lane = tid & 31;
    const int gr   = lane >> 2;
    const int q    = lane & 3;

    const int sw    = lane & 7;
    const int rbase = (8*(lane >> 4) + sw) * 32;
    const int kb    = (lane >> 3) & 1;

    // ---- Q fragments (hi/lo), rows 16wp+{gr,gr+8} ----
    const float* Qb = g_Q + ((size_t)(b*Nn + q0 + 16*wp))*Cn;
    unsigned aQh[4][4], aQl[4][4];
    #pragma unroll
    for (int ks = 0; ks < 4; ks++) {
        const float* r0 = Qb + gr*64;
        const float* r1 = Qb + (gr + 8)*64;
        float2 v;
        v = *(const float2*)(r0 + 16*ks + 2*q);     bsplit2(v.x, v.y, aQh[ks][0], aQl[ks][0]);
        v = *(const float2*)(r1 + 16*ks + 2*q);     bsplit2(v.x, v.y, aQh[ks][1], aQl[ks][1]);
        v = *(const float2*)(r0 + 16*ks + 8 + 2*q); bsplit2(v.x, v.y, aQh[ks][2], aQl[ks][2]);
        v = *(const float2*)(r1 + 16*ks + 8 + 2*q); bsplit2(v.x, v.y, aQh[ks][3], aQl[ks][3]);
    }

    float oA[8][4];
    #pragma unroll
    for (int j = 0; j < 8; j++)
        #pragma unroll
        for (int i = 0; i < 4; i++) oA[j][i] = 0.0f;
    float l0 = 0.0f, l1 = 0.0f;

    const uint4* Kh4 = (const uint4*)(g_Kh + (size_t)b*Nn*Cn);
    const uint4* Kl4 = (const uint4*)(g_Kl + (size_t)b*Nn*Cn);
    const uint4* Vh4 = (const uint4*)(g_Vh + (size_t)b*Cn*Nn);
    const uint4* Vl4 = (const uint4*)(g_Vl + (size_t)b*Cn*Nn);

    auto issue_tile = [&](int kt, int bufsel) {
        unsigned* base = smem + bufsel*8192;
        #pragma unroll
        for (int it = 0; it < 4; it++) {
            const int f   = tid + it*128;
            const int row = f >> 3;
            const int ch  = f & 7;
            const int dw  = row*32 + ((ch ^ (row & 7)) << 2);
            cpa16(&base[dw],        Kh4 + kt*512 + row*8 + ch);
            cpa16(&base[2048 + dw], Kl4 + kt*512 + row*8 + ch);
            cpa16(&base[4096 + dw], Vh4 + row*(Nn/8) + kt*8 + ch);
            cpa16(&base[6144 + dw], Vl4 + row*(Nn/8) + kt*8 + ch);
        }
        asm volatile("cp.async.commit_group;" ::: "memory");
    };

    issue_tile(0, 0);
    int buf = 0;

    for (int kt = 0; kt < NT; kt++) {
        asm volatile("cp.async.wait_group 0;" ::: "memory");
        __syncthreads();
        if (kt + 1 < NT) issue_tile(kt + 1, buf ^ 1);

        const unsigned* sKh = smem + buf*8192;
        const unsigned* sVh = sKh + 4096;

        // ---- per pair of 16-key blocks: S (4 chains) -> exp -> 2 PV k-steps
        #pragma unroll
        for (int jph = 0; jph < 2; jph++) {
            const int jp0 = 2*jph, jp1 = 2*jph + 1;
            float sa0[4] = {0.f,0.f,0.f,0.f}, sa1[4] = {0.f,0.f,0.f,0.f};
            float sb0[4] = {0.f,0.f,0.f,0.f}, sb1[4] = {0.f,0.f,0.f,0.f};
            #pragma unroll
            for (int ks = 0; ks < 4; ks++) {
                const int co = (((2*ks + kb) ^ sw) << 2) + rbase;
                const unsigned* p0 = sKh + jp0*512 + co;
                const unsigned* p1 = sKh + jp1*512 + co;
                PAIR3_X2(sa0, sa1, sb0, sb1, aQh[ks], aQl[ks],
                         p0, p0 + 2048, p1, p1 + 2048);
            }

            // exp (base-2) + row sums, order matches single-jp version
            sa0[0] = ex2(sa0[0]); sa0[1] = ex2(sa0[1]);
            sa0[2] = ex2(sa0[2]); sa0[3] = ex2(sa0[3]);
            l0 += sa0[0] + sa0[1];
            l1 += sa0[2] + sa0[3];
            sa1[0] = ex2(sa1[0]); sa1[1] = ex2(sa1[1]);
            sa1[2] = ex2(sa1[2]); sa1[3] = ex2(sa1[3]);
            l0 += sa1[0] + sa1[1];
            l1 += sa1[2] + sa1[3];
            sb0[0] = ex2(sb0[0]); sb0[1] = ex2(sb0[1]);
            sb0[2] = ex2(sb0[2]); sb0[3] = ex2(sb0[3]);
            l0 += sb0[0] + sb0[1];
            l1 += sb0[2] + sb0[3];
            sb1[0] = ex2(sb1[0]); sb1[1] = ex2(sb1[1]);
            sb1[2] = ex2(sb1[2]); sb1[3] = ex2(sb1[3]);
            l0 += sb1[0] + sb1[1];
            l1 += sb1[2] + sb1[3];

            unsigned aPh0[4], aPl0[4], aPh1[4], aPl1[4];
            bsplit2(sa0[0], sa0[1], aPh0[0], aPl0[0]);
            bsplit2(sa0[2], sa0[3], aPh0[1], aPl0[1]);
            bsplit2(sa1[0], sa1[1], aPh0[2], aPl0[2]);
            bsplit2(sa1[2], sa1[3], aPh0[3], aPl0[3]);
            bsplit2(sb0[0], sb0[1], aPh1[0], aPl1[0]);
            bsplit2(sb0[2], sb0[3], aPh1[1], aPl1[1]);
            bsplit2(sb1[0], sb1[1], aPh1[2], aPl1[2]);
            bsplit2(sb1[2], sb1[3], aPh1[3], aPl1[3]);

            // PV k-step jp0 then jp1 (accumulation order preserved)
            const int cov0 = (((2*jp0 + kb) ^ sw) << 2) + rbase;
            #pragma unroll
            for (int jv = 0; jv < 4; jv++) {
                const unsigned* p = sVh + jv*512 + cov0;
                PAIR3(oA[2*jv], oA[2*jv + 1], aPh0, aPl0, p, p + 2048);
            }
            const int cov1 = (((2*jp1 + kb) ^ sw) << 2) + rbase;
            #pragma unroll
            for (int jv = 0; jv < 4; jv++) {
                const unsigned* p = sVh + jv*512 + cov1;
                PAIR3(oA[2*jv], oA[2*jv + 1], aPh1, aPl1, p, p + 2048);
            }
        }

        buf ^= 1;
    }

    // ============= epilogue: ctx = O/l; out = ctx @ Wp + bp =============
    l0 += __shfl_xor_sync(0xffffffffu, l0, 1);
    l0 += __shfl_xor_sync(0xffffffffu, l0, 2);
    l1 += __shfl_xor_sync(0xffffffffu, l1, 1);
    l1 += __shfl_xor_sync(0xffffffffu, l1, 2);
    const float inv0 = 1.0f / l0;
    const float inv1 = 1.0f / l1;

    __syncthreads();
    __nv_bfloat16* sWh = (__nv_bfloat16*)smem;
    __nv_bfloat16* sWl = (__nv_bfloat16*)(smem + 2048);
    for (int i = tid; i < 4096; i += 128) {
        const int c = i >> 6, e = i & 63;
        const float wv = Wp[i];
        __nv_bfloat16 hb = __float2bfloat16(wv);
        const int o = e*64 + ((((c >> 3) ^ (e & 7))) << 3) + (c & 7);
        sWh[o] = hb;
        sWl[o] = __float2bfloat16(wv - __bfloat162float(hb));
    }
    __syncthreads();

    float pA[8][4];
    #pragma unroll
    for (int j = 0; j < 8; j++)
        #pragma unroll
        for (int i = 0; i < 4; i++) pA[j][i] = 0.0f;
    #pragma unroll
    for (int ks = 0; ks < 4; ks++) {
        unsigned aCh[4], aCl[4];
        bsplit2(oA[2*ks    ][0]*inv0, oA[2*ks    ][1]*inv0, aCh[0], aCl[0]);
        bsplit2(oA[2*ks    ][2]*inv1, oA[2*ks    ][3]*inv1, aCh[1], aCl[1]);
        bsplit2(oA[2*ks + 1][0]*inv0, oA[2*ks + 1][1]*inv0, aCh[2], aCl[2]);
        bsplit2(oA[2*ks + 1][2]*inv1, oA[2*ks + 1][3]*inv1, aCh[3], aCl[3]);
        const int co = (((2*ks + kb) ^ sw) << 2) + rbase;
        #pragma unroll
        for (int jp = 0; jp < 4; jp++) {
            const unsigned* p = smem + jp*512 + co;
            PAIR3(pA[2*jp], pA[2*jp + 1], aCh, aCl, p, p + 2048);
        }
    }

    float* orow0 = out + (size_t)(b*Nn + q0 + 16*wp + gr)*En;
    float* orow1 = orow0 + 8*En;
    #pragma unroll
    for (int j = 0; j < 8; j++) {
        const float2 bv = *(const float2*)&bp[8*j + 2*q];
        *(float2*)&orow0[8*j + 2*q] = make_float2(pA[j][0] + bv.x, pA[j][1] + bv.y);
        *(float2*)&orow1[8*j + 2*q] = make_float2(pA[j][2] + bv.x, pA[j][3] + bv.y);
    }
}

// ---------------------------------------------------------------------------
extern "C" void kernel_launch(void* const* d_in, const int* in_sizes, int n_in,
                              void* d_out, int out_size)
{
    const float* x  = (const float*)d_in[0];
    const float* wq = (const float*)d_in[1];
    const float* bq = (const float*)d_in[2];
    const float* wk = (const float*)d_in[3];
    const float* bk = (const float*)d_in[4];
    const float* wv = (const float*)d_in[5];
    const float* bv = (const float*)d_in[6];
    const float* Wp = (const float*)d_in[7];
    const float* bp = (const float*)d_in[8];
    float* out = (float*)d_out;

    const int conv_smem = (27*Cn + 3*Wn*RS) * 4;   // 50592
    cudaFuncSetAttribute(qkv_conv_kernel,
                         cudaFuncAttributeMaxDynamicSharedMemorySize, conv_smem);
    const int smem_bytes = 2*8192*4;   // 65536
    cudaFuncSetAttribute(attn_kernel,
                         cudaFuncAttributeMaxDynamicSharedMemorySize, smem_bytes);

    qkv_conv_kernel<<<Bn*Hn, 256, conv_smem>>>(x, wq, bq, wk, bk, wv, bv);

    dim3 grid(NT, Bn);
    attn_kernel<<<grid, 128, smem_bytes>>>(Wp, bp, out);
}